// round 1
// baseline (speedup 1.0000x reference)
#include <cuda_runtime.h>
#include <math.h>

// Problem constants (fixed by reference setup_inputs)
#define Bc   2
#define Lc   2048
#define Dc   1024
#define Nc   16
#define Fc   4096
#define TOK  (Bc*Lc)          // 4096 tokens
#define EPSF 1e-6f

// ---------------- scratch (no allocation allowed) ----------------
__device__ float g_xn [TOK*Dc];   // rmsnorm1 output
__device__ float g_dt [TOK*Dc];   // softplus(xn@Wdt^T+bdt)
__device__ float g_x2 [TOK*Dc];   // mamba out + residual
__device__ float g_xn2[TOK*Dc];   // rmsnorm2 output
__device__ float g_Bv [TOK*Nc];
__device__ float g_Cv [TOK*Nc];
__device__ float g_h  [TOK*Fc];   // FFN hidden

// ---------------- helpers ----------------
__device__ __forceinline__ float softplus_f(float v) {
    // log1p(exp(v)), stable
    return fmaxf(v, 0.0f) + log1pf(__expf(-fabsf(v)));
}
__device__ __forceinline__ float gelu_f(float v) {
    const float c = 0.7978845608028654f; // sqrt(2/pi)
    float u = c * (v + 0.044715f * v * v * v);
    return 0.5f * v * (1.0f + tanhf(u));
}

// ---------------- rmsnorm: one block per token, 256 threads ----------------
__global__ void rmsnorm_kernel(const float* __restrict__ x,
                               const float* __restrict__ w,
                               float* __restrict__ out)
{
    __shared__ float red[8];
    const int t = blockIdx.x;
    const int tid = threadIdx.x;
    const float4 a = reinterpret_cast<const float4*>(x + (size_t)t * Dc)[tid];
    float ss = a.x*a.x + a.y*a.y + a.z*a.z + a.w*a.w;
#pragma unroll
    for (int o = 16; o; o >>= 1) ss += __shfl_xor_sync(0xffffffffu, ss, o);
    if ((tid & 31) == 0) red[tid >> 5] = ss;
    __syncthreads();
    if (tid < 8) {
        float v = red[tid];
#pragma unroll
        for (int o = 4; o; o >>= 1) v += __shfl_xor_sync(0xffu, v, o);
        if (tid == 0) red[0] = v;
    }
    __syncthreads();
    const float inv = rsqrtf(red[0] * (1.0f / Dc) + EPSF);
    const float4 wv = reinterpret_cast<const float4*>(w)[tid];
    float4 o4;
    o4.x = a.x * inv * wv.x;
    o4.y = a.y * inv * wv.y;
    o4.z = a.z * inv * wv.z;
    o4.w = a.w * inv * wv.w;
    reinterpret_cast<float4*>(out + (size_t)t * Dc)[tid] = o4;
}

// ---------------- SGEMM: C[M,Nout] = X[M,K] @ W[Nout,K]^T, fused epilogue ----------------
// 128x128 tile, BK=8, 256 threads, 8x8 micro-tile with split-64 fragment mapping.
// EPI: 1 = softplus(v+bias)   2 = gelu(v+bias)   3 = v+bias+res
template<int EPI>
__global__ __launch_bounds__(256, 2)
void sgemm128(const float* __restrict__ X, const float* __restrict__ W,
              const float* __restrict__ bias, const float* __restrict__ res,
              float* __restrict__ C, int M, int Nout, int K)
{
    __shared__ float Xs[8][128];
    __shared__ float Ws[8][128];
    const int tid = threadIdx.x;
    const int m0 = blockIdx.y * 128, n0 = blockIdx.x * 128;
    const int lr = tid >> 1;           // 0..127 tile row
    const int lc = (tid & 1) * 4;      // 0 or 4 (k sub-chunk)
    const float* Xg = X + (size_t)(m0 + lr) * K + lc;
    const float* Wg = W + (size_t)(n0 + lr) * K + lc;
    const int ty = tid >> 4, tx = tid & 15;

    float acc[8][8];
#pragma unroll
    for (int i = 0; i < 8; i++)
#pragma unroll
        for (int j = 0; j < 8; j++) acc[i][j] = 0.0f;

    for (int k0 = 0; k0 < K; k0 += 8) {
        const float4 xa = *reinterpret_cast<const float4*>(Xg + k0);
        const float4 wa = *reinterpret_cast<const float4*>(Wg + k0);
        __syncthreads();
        Xs[lc + 0][lr] = xa.x; Xs[lc + 1][lr] = xa.y;
        Xs[lc + 2][lr] = xa.z; Xs[lc + 3][lr] = xa.w;
        Ws[lc + 0][lr] = wa.x; Ws[lc + 1][lr] = wa.y;
        Ws[lc + 2][lr] = wa.z; Ws[lc + 3][lr] = wa.w;
        __syncthreads();
#pragma unroll
        for (int k = 0; k < 8; k++) {
            float af[8], bf[8];
            *reinterpret_cast<float4*>(af)     = *reinterpret_cast<const float4*>(&Xs[k][ty * 4]);
            *reinterpret_cast<float4*>(af + 4) = *reinterpret_cast<const float4*>(&Xs[k][64 + ty * 4]);
            *reinterpret_cast<float4*>(bf)     = *reinterpret_cast<const float4*>(&Ws[k][tx * 4]);
            *reinterpret_cast<float4*>(bf + 4) = *reinterpret_cast<const float4*>(&Ws[k][64 + tx * 4]);
#pragma unroll
            for (int i = 0; i < 8; i++)
#pragma unroll
                for (int j = 0; j < 8; j++)
                    acc[i][j] = fmaf(af[i], bf[j], acc[i][j]);
        }
    }

#pragma unroll
    for (int i = 0; i < 8; i++) {
        const int m = m0 + ((i < 4) ? (ty * 4 + i) : (64 + ty * 4 + (i - 4)));
#pragma unroll
        for (int jh = 0; jh < 2; jh++) {
            const int nb = n0 + ((jh == 0) ? (tx * 4) : (64 + tx * 4));
            float4 o;
            float* oo = &o.x;
#pragma unroll
            for (int q = 0; q < 4; q++) {
                const int n = nb + q;
                float v = acc[i][jh * 4 + q] + bias[n];
                if (EPI == 1)      v = softplus_f(v);
                else if (EPI == 2) v = gelu_f(v);
                else if (EPI == 3) v += res[(size_t)m * Nout + n];
                oo[q] = v;
            }
            *reinterpret_cast<float4*>(&C[(size_t)m * Nout + nb]) = o;
        }
    }
}

// ---------------- B/C projections: one block per token ----------------
__global__ void bc_kernel(const float* __restrict__ xn,
                          const float* __restrict__ WB, const float* __restrict__ bB,
                          const float* __restrict__ WC, const float* __restrict__ bC,
                          float* __restrict__ Bv, float* __restrict__ Cv)
{
    __shared__ float xs[Dc];
    const int t = blockIdx.x;
    const int tid = threadIdx.x;
    reinterpret_cast<float4*>(xs)[tid] =
        reinterpret_cast<const float4*>(xn + (size_t)t * Dc)[tid];
    __syncthreads();

    const int o = tid >> 3;   // 0..31: 0-15 -> Bv rows, 16-31 -> Cv rows
    const int p = tid & 7;
    const float* w = (o < Nc) ? (WB + (size_t)o * Dc) : (WC + (size_t)(o - Nc) * Dc);
    float s = 0.0f;
#pragma unroll 8
    for (int k = p; k < Dc; k += 8) s = fmaf(xs[k], w[k], s);
    s += __shfl_xor_sync(0xffffffffu, s, 1);
    s += __shfl_xor_sync(0xffffffffu, s, 2);
    s += __shfl_xor_sync(0xffffffffu, s, 4);
    if (p == 0) {
        if (o < Nc) Bv[(size_t)t * Nc + o] = s + bB[o];
        else        Cv[(size_t)t * Nc + (o - Nc)] = s + bC[o - Nc];
    }
}

// ---------------- selective scan: lane per (b,d,n), 16-lane segments ----------------
// out[b,l,d] = (sum_n Cv[b,l,n]*h[b,l,d,n] + Dp[d]*xn[b,l,d]) * scale[d] + res[b,l,d]
// h_{l} = exp(dt*A_n) * h_{l-1} + phi1(dt*A_n) * Bv_n * xn
__global__ void scan_kernel(const float* __restrict__ dt, const float* __restrict__ xn,
                            const float* __restrict__ Bv, const float* __restrict__ Cv,
                            const float* __restrict__ A_log, const float* __restrict__ Dp,
                            const float* __restrict__ scale, const float* __restrict__ resid,
                            float* __restrict__ out)
{
    const int tid = threadIdx.x;
    const int n = tid & 15;
    const int g = blockIdx.x * (blockDim.x >> 4) + (tid >> 4); // (b,d) group, 0..2047
    const int b = g >> 10;
    const int d = g & 1023;

    const float An  = -__expf(A_log[n]);
    const float Dpv = Dp[d];
    const float sc  = scale[d];

    const float* dtp = dt    + (size_t)b * Lc * Dc + d;
    const float* xnp = xn    + (size_t)b * Lc * Dc + d;
    const float* rpp = resid + (size_t)b * Lc * Dc + d;
    float*       opp = out   + (size_t)b * Lc * Dc + d;
    const float* bpp = Bv    + (size_t)b * Lc * Nc + n;
    const float* cpp = Cv    + (size_t)b * Lc * Nc + n;

    float h = 0.0f;
#pragma unroll 2
    for (int l = 0; l < Lc; l++) {
        const float dtv = dtp[(size_t)l * Dc];
        const float xv  = xnp[(size_t)l * Dc];
        const float bv  = bpp[(size_t)l * Nc];
        const float cv  = cpp[(size_t)l * Nc];

        const float z = dtv * An;
        const float e = __expf(z);
        const float phi = (fabsf(z) < 1e-4f) ? fmaf(0.5f, z, 1.0f)
                                             : __fdividef(e - 1.0f, z);
        h = fmaf(e, h, phi * bv * xv);

        float p = cv * h;
        p += __shfl_xor_sync(0xffffffffu, p, 1);
        p += __shfl_xor_sync(0xffffffffu, p, 2);
        p += __shfl_xor_sync(0xffffffffu, p, 4);
        p += __shfl_xor_sync(0xffffffffu, p, 8);
        if (n == 0) {
            const float r = rpp[(size_t)l * Dc];
            opp[(size_t)l * Dc] = fmaf(fmaf(Dpv, xv, p), sc, r);
        }
    }
}

// ---------------- launch ----------------
extern "C" void kernel_launch(void* const* d_in, const int* in_sizes, int n_in,
                              void* d_out, int out_size)
{
    const float* x     = (const float*)d_in[0];
    const float* n1w   = (const float*)d_in[1];
    const float* n2w   = (const float*)d_in[2];
    const float* A_log = (const float*)d_in[3];
    const float* Dp    = (const float*)d_in[4];
    const float* scale = (const float*)d_in[5];
    const float* Wdt   = (const float*)d_in[6];
    const float* bdt   = (const float*)d_in[7];
    const float* WB    = (const float*)d_in[8];
    const float* bB    = (const float*)d_in[9];
    const float* WC    = (const float*)d_in[10];
    const float* bC    = (const float*)d_in[11];
    const float* W1    = (const float*)d_in[12];
    const float* b1    = (const float*)d_in[13];
    const float* W2    = (const float*)d_in[14];
    const float* b2    = (const float*)d_in[15];
    float* out = (float*)d_out;

    float *xn, *dt, *x2, *xn2, *Bv, *Cv, *hb;
    cudaGetSymbolAddress((void**)&xn,  g_xn);
    cudaGetSymbolAddress((void**)&dt,  g_dt);
    cudaGetSymbolAddress((void**)&x2,  g_x2);
    cudaGetSymbolAddress((void**)&xn2, g_xn2);
    cudaGetSymbolAddress((void**)&Bv,  g_Bv);
    cudaGetSymbolAddress((void**)&Cv,  g_Cv);
    cudaGetSymbolAddress((void**)&hb,  g_h);

    // 1) xn = rmsnorm(x, norm1_w)
    rmsnorm_kernel<<<TOK, 256>>>(x, n1w, xn);
    // 2) dt = softplus(xn @ Wdt^T + bdt)
    sgemm128<1><<<dim3(Dc / 128, TOK / 128), 256>>>(xn, Wdt, bdt, nullptr, dt, TOK, Dc, Dc);
    // 3) Bv, Cv projections
    bc_kernel<<<TOK, 256>>>(xn, WB, bB, WC, bC, Bv, Cv);
    // 4) selective scan + D-skip + scale + residual -> x2
    scan_kernel<<<(Bc * Dc) / 16, 256>>>(dt, xn, Bv, Cv, A_log, Dp, scale, x, x2);
    // 5) xn2 = rmsnorm(x2, norm2_w)
    rmsnorm_kernel<<<TOK, 256>>>(x2, n2w, xn2);
    // 6) h = gelu(xn2 @ W1^T + b1)
    sgemm128<2><<<dim3(Fc / 128, TOK / 128), 256>>>(xn2, W1, b1, nullptr, hb, TOK, Fc, Dc);
    // 7) out = h @ W2^T + b2 + x2
    sgemm128<3><<<dim3(Dc / 128, TOK / 128), 256>>>(hb, W2, b2, x2, out, TOK, Dc, Fc);
}

// round 3
// speedup vs baseline: 1.6760x; 1.6760x over previous
#include <cuda_runtime.h>
#include <math.h>
#include <stdint.h>

// Problem constants (fixed by reference setup_inputs)
#define Bc   2
#define Lc   2048
#define Dc   1024
#define Nc   16
#define Fc   4096
#define TOK  (Bc*Lc)          // 4096 tokens
#define EPSF 1e-6f

// ---------------- scratch (no allocation allowed) ----------------
__device__ float g_xn [TOK*Dc];   // rmsnorm1 output
__device__ float g_dt [TOK*Dc];   // softplus(xn@Wdt^T+bdt)
__device__ float g_x2 [TOK*Dc];   // mamba out + residual
__device__ float g_xn2[TOK*Dc];   // rmsnorm2 output
__device__ float g_Bv [TOK*Nc];
__device__ float g_Cv [TOK*Nc];
__device__ float g_h  [TOK*Fc];   // FFN hidden

// ---------------- helpers ----------------
__device__ __forceinline__ float softplus_f(float v) {
    return fmaxf(v, 0.0f) + log1pf(__expf(-fabsf(v)));
}
__device__ __forceinline__ float gelu_f(float v) {
    const float c = 0.7978845608028654f; // sqrt(2/pi)
    float u = c * (v + 0.044715f * v * v * v);
    return 0.5f * v * (1.0f + tanhf(u));
}
__device__ __forceinline__ uint32_t f2tf(float x) {
    uint32_t r;
    asm("cvt.rna.tf32.f32 %0, %1;" : "=r"(r) : "f"(x));
    return r;
}
__device__ __forceinline__ void mma8(float* d, const uint32_t* a, const uint32_t* b) {
    asm volatile(
        "mma.sync.aligned.m16n8k8.row.col.f32.tf32.tf32.f32 "
        "{%0,%1,%2,%3}, {%4,%5,%6,%7}, {%8,%9}, {%0,%1,%2,%3};"
        : "+f"(d[0]), "+f"(d[1]), "+f"(d[2]), "+f"(d[3])
        : "r"(a[0]), "r"(a[1]), "r"(a[2]), "r"(a[3]), "r"(b[0]), "r"(b[1]));
}

#define CPA(s,g)      asm volatile("cp.async.cg.shared.global [%0], [%1], 16;" :: "r"(s), "l"(g))
#define CPA_COMMIT()  asm volatile("cp.async.commit_group;" ::: "memory")
#define CPA_WAIT1()   asm volatile("cp.async.wait_group 1;" ::: "memory")
#define CPA_WAIT0()   asm volatile("cp.async.wait_group 0;" ::: "memory")

__device__ __forceinline__ uint32_t smem_u32(const void* p) {
    uint32_t a;
    asm("{ .reg .u64 t; cvta.to.shared.u64 t, %1; cvt.u32.u64 %0, t; }" : "=r"(a) : "l"(p));
    return a;
}

// ---------------- rmsnorm: one block per token, 256 threads ----------------
__global__ void rmsnorm_kernel(const float* __restrict__ x,
                               const float* __restrict__ w,
                               float* __restrict__ out)
{
    __shared__ float red[8];
    const int t = blockIdx.x;
    const int tid = threadIdx.x;
    const float4 a = reinterpret_cast<const float4*>(x + (size_t)t * Dc)[tid];
    float ss = a.x*a.x + a.y*a.y + a.z*a.z + a.w*a.w;
#pragma unroll
    for (int o = 16; o; o >>= 1) ss += __shfl_xor_sync(0xffffffffu, ss, o);
    if ((tid & 31) == 0) red[tid >> 5] = ss;
    __syncthreads();
    if (tid < 8) {
        float v = red[tid];
#pragma unroll
        for (int o = 4; o; o >>= 1) v += __shfl_xor_sync(0xffu, v, o);
        if (tid == 0) red[0] = v;
    }
    __syncthreads();
    const float inv = rsqrtf(red[0] * (1.0f / Dc) + EPSF);
    const float4 wv = reinterpret_cast<const float4*>(w)[tid];
    float4 o4;
    o4.x = a.x * inv * wv.x;
    o4.y = a.y * inv * wv.y;
    o4.z = a.z * inv * wv.z;
    o4.w = a.w * inv * wv.w;
    reinterpret_cast<float4*>(out + (size_t)t * Dc)[tid] = o4;
}

// ---------------- mma.sync tf32 GEMM: C[M,Nout] = X[M,K] @ W[Nout,K]^T ----------------
// 128x128 CTA tile, BK=32, 8 warps (2x4), warp tile 64x32 (4x4 m16n8k8 frags).
// Smem rows padded to 36 floats -> all fragment LDS are bank-conflict-free.
// EPI: 1 = softplus(v+bias)  2 = gelu(v+bias)  3 = v+bias+res
#define LDST  36            // padded row stride (floats)
#define BUFSZ (128 * LDST)  // one A or B buffer (floats)

template<int EPI>
__global__ __launch_bounds__(256)
void mma_gemm(const float* __restrict__ X, const float* __restrict__ W,
              const float* __restrict__ bias, const float* __restrict__ res,
              float* __restrict__ C, int M, int Nout, int K)
{
    extern __shared__ float sm[];
    float* As = sm;                 // [2][BUFSZ]
    float* Bs = sm + 2 * BUFSZ;     // [2][BUFSZ]

    const int tid = threadIdx.x;
    const int wid = tid >> 5, lane = tid & 31;
    const int wm = wid >> 2, wn = wid & 3;         // 2 x 4 warp grid
    const int g = lane >> 2, tg = lane & 3;
    const int m0 = blockIdx.y * 128, n0 = blockIdx.x * 128;

    // cp.async destination indices for this thread (4 float4 per matrix per stage)
    const uint32_t asmb = smem_u32(As);
    const uint32_t bsmb = smem_u32(Bs);

    auto load_stage = [&](int s, int buf) {
        const int k0 = s << 5;
        const uint32_t ab = asmb + (uint32_t)buf * (BUFSZ * 4);
        const uint32_t bb = bsmb + (uint32_t)buf * (BUFSZ * 4);
#pragma unroll
        for (int j = 0; j < 4; j++) {
            const int i = tid + (j << 8);          // 0..1023
            const int r = i >> 3, c = i & 7;       // row 0..127, float4 col 0..7
            const uint32_t so = (uint32_t)(r * LDST + c * 4) * 4u;
            CPA(ab + so, X + (size_t)(m0 + r) * K + k0 + c * 4);
            CPA(bb + so, W + (size_t)(n0 + r) * K + k0 + c * 4);
        }
        CPA_COMMIT();
    };

    float acc[4][4][4];
#pragma unroll
    for (int i = 0; i < 4; i++)
#pragma unroll
        for (int j = 0; j < 4; j++)
#pragma unroll
            for (int q = 0; q < 4; q++) acc[i][j][q] = 0.0f;

    const int S = K >> 5;
    load_stage(0, 0);

    for (int s = 0; s < S; s++) {
        const int buf = s & 1;
        if (s + 1 < S) { load_stage(s + 1, buf ^ 1); CPA_WAIT1(); }
        else           { CPA_WAIT0(); }
        __syncthreads();

        const float* Ab = As + buf * BUFSZ;
        const float* Bb = Bs + buf * BUFSZ;
#pragma unroll
        for (int ks = 0; ks < 4; ks++) {
            uint32_t af[4][4], bf[4][2];
#pragma unroll
            for (int i = 0; i < 4; i++) {
                const float* p = Ab + (wm * 64 + i * 16 + g) * LDST + ks * 8 + tg;
                af[i][0] = f2tf(p[0]);
                af[i][1] = f2tf(p[8 * LDST]);
                af[i][2] = f2tf(p[4]);
                af[i][3] = f2tf(p[8 * LDST + 4]);
            }
#pragma unroll
            for (int j = 0; j < 4; j++) {
                const float* p = Bb + (wn * 32 + j * 8 + g) * LDST + ks * 8 + tg;
                bf[j][0] = f2tf(p[0]);
                bf[j][1] = f2tf(p[4]);
            }
#pragma unroll
            for (int i = 0; i < 4; i++)
#pragma unroll
                for (int j = 0; j < 4; j++) mma8(acc[i][j], af[i], bf[j]);
        }
        __syncthreads();
    }

    // Epilogue: c0,c1 at (row g, cols 2tg,2tg+1); c2,c3 at row g+8.
#pragma unroll
    for (int i = 0; i < 4; i++) {
        const int mA = m0 + wm * 64 + i * 16 + g;
#pragma unroll
        for (int j = 0; j < 4; j++) {
            const int nA = n0 + wn * 32 + j * 8 + tg * 2;
            const float2 bb = *reinterpret_cast<const float2*>(bias + nA);
#pragma unroll
            for (int h = 0; h < 2; h++) {
                const int m = mA + h * 8;
                float v0 = acc[i][j][h * 2 + 0] + bb.x;
                float v1 = acc[i][j][h * 2 + 1] + bb.y;
                if (EPI == 1) { v0 = softplus_f(v0); v1 = softplus_f(v1); }
                else if (EPI == 2) { v0 = gelu_f(v0); v1 = gelu_f(v1); }
                else if (EPI == 3) {
                    const float2 r2 = *reinterpret_cast<const float2*>(res + (size_t)m * Nout + nA);
                    v0 += r2.x; v1 += r2.y;
                }
                *reinterpret_cast<float2*>(C + (size_t)m * Nout + nA) = make_float2(v0, v1);
            }
        }
    }
}

// ---------------- B/C projections: one block per token ----------------
__global__ void bc_kernel(const float* __restrict__ xn,
                          const float* __restrict__ WB, const float* __restrict__ bB,
                          const float* __restrict__ WC, const float* __restrict__ bC,
                          float* __restrict__ Bv, float* __restrict__ Cv)
{
    __shared__ float xs[Dc];
    const int t = blockIdx.x;
    const int tid = threadIdx.x;
    reinterpret_cast<float4*>(xs)[tid] =
        reinterpret_cast<const float4*>(xn + (size_t)t * Dc)[tid];
    __syncthreads();

    const int o = tid >> 3;
    const int p = tid & 7;
    const float* w = (o < Nc) ? (WB + (size_t)o * Dc) : (WC + (size_t)(o - Nc) * Dc);
    float s = 0.0f;
#pragma unroll 8
    for (int k = p; k < Dc; k += 8) s = fmaf(xs[k], w[k], s);
    s += __shfl_xor_sync(0xffffffffu, s, 1);
    s += __shfl_xor_sync(0xffffffffu, s, 2);
    s += __shfl_xor_sync(0xffffffffu, s, 4);
    if (p == 0) {
        if (o < Nc) Bv[(size_t)t * Nc + o] = s + bB[o];
        else        Cv[(size_t)t * Nc + (o - Nc)] = s + bC[o - Nc];
    }
}

// ---------------- selective scan: lane per (b,d,n), 16-lane segments ----------------
__global__ void scan_kernel(const float* __restrict__ dt, const float* __restrict__ xn,
                            const float* __restrict__ Bv, const float* __restrict__ Cv,
                            const float* __restrict__ A_log, const float* __restrict__ Dp,
                            const float* __restrict__ scale, const float* __restrict__ resid,
                            float* __restrict__ out)
{
    const int tid = threadIdx.x;
    const int n = tid & 15;
    const int g = blockIdx.x * (blockDim.x >> 4) + (tid >> 4);
    const int b = g >> 10;
    const int d = g & 1023;

    const float An  = -__expf(A_log[n]);
    const float Dpv = Dp[d];
    const float sc  = scale[d];

    const float* dtp = dt    + (size_t)b * Lc * Dc + d;
    const float* xnp = xn    + (size_t)b * Lc * Dc + d;
    const float* rpp = resid + (size_t)b * Lc * Dc + d;
    float*       opp = out   + (size_t)b * Lc * Dc + d;
    const float* bpp = Bv    + (size_t)b * Lc * Nc + n;
    const float* cpp = Cv    + (size_t)b * Lc * Nc + n;

    float h = 0.0f;
#pragma unroll 2
    for (int l = 0; l < Lc; l++) {
        const float dtv = dtp[(size_t)l * Dc];
        const float xv  = xnp[(size_t)l * Dc];
        const float bv  = bpp[(size_t)l * Nc];
        const float cv  = cpp[(size_t)l * Nc];

        const float z = dtv * An;
        const float e = __expf(z);
        const float phi = (fabsf(z) < 1e-4f) ? fmaf(0.5f, z, 1.0f)
                                             : __fdividef(e - 1.0f, z);
        h = fmaf(e, h, phi * bv * xv);

        float p = cv * h;
        p += __shfl_xor_sync(0xffffffffu, p, 1);
        p += __shfl_xor_sync(0xffffffffu, p, 2);
        p += __shfl_xor_sync(0xffffffffu, p, 4);
        p += __shfl_xor_sync(0xffffffffu, p, 8);
        if (n == 0) {
            const float r = rpp[(size_t)l * Dc];
            opp[(size_t)l * Dc] = fmaf(fmaf(Dpv, xv, p), sc, r);
        }
    }
}

// ---------------- launch ----------------
extern "C" void kernel_launch(void* const* d_in, const int* in_sizes, int n_in,
                              void* d_out, int out_size)
{
    const float* x     = (const float*)d_in[0];
    const float* n1w   = (const float*)d_in[1];
    const float* n2w   = (const float*)d_in[2];
    const float* A_log = (const float*)d_in[3];
    const float* Dp    = (const float*)d_in[4];
    const float* scale = (const float*)d_in[5];
    const float* Wdt   = (const float*)d_in[6];
    const float* bdt   = (const float*)d_in[7];
    const float* WB    = (const float*)d_in[8];
    const float* bB    = (const float*)d_in[9];
    const float* WC    = (const float*)d_in[10];
    const float* bC    = (const float*)d_in[11];
    const float* W1    = (const float*)d_in[12];
    const float* b1    = (const float*)d_in[13];
    const float* W2    = (const float*)d_in[14];
    const float* b2    = (const float*)d_in[15];
    float* out = (float*)d_out;

    float *xn, *dt, *x2, *xn2, *Bv, *Cv, *hb;
    cudaGetSymbolAddress((void**)&xn,  g_xn);
    cudaGetSymbolAddress((void**)&dt,  g_dt);
    cudaGetSymbolAddress((void**)&x2,  g_x2);
    cudaGetSymbolAddress((void**)&xn2, g_xn2);
    cudaGetSymbolAddress((void**)&Bv,  g_Bv);
    cudaGetSymbolAddress((void**)&Cv,  g_Cv);
    cudaGetSymbolAddress((void**)&hb,  g_h);

    const int SMEM = 4 * BUFSZ * 4;   // 73728 B
    cudaFuncSetAttribute(mma_gemm<1>, cudaFuncAttributeMaxDynamicSharedMemorySize, SMEM);
    cudaFuncSetAttribute(mma_gemm<2>, cudaFuncAttributeMaxDynamicSharedMemorySize, SMEM);
    cudaFuncSetAttribute(mma_gemm<3>, cudaFuncAttributeMaxDynamicSharedMemorySize, SMEM);

    // 1) xn = rmsnorm(x, norm1_w)
    rmsnorm_kernel<<<TOK, 256>>>(x, n1w, xn);
    // 2) dt = softplus(xn @ Wdt^T + bdt)
    mma_gemm<1><<<dim3(Dc / 128, TOK / 128), 256, SMEM>>>(xn, Wdt, bdt, nullptr, dt, TOK, Dc, Dc);
    // 3) Bv, Cv projections
    bc_kernel<<<TOK, 256>>>(xn, WB, bB, WC, bC, Bv, Cv);
    // 4) selective scan + D-skip + scale + residual -> x2
    scan_kernel<<<(Bc * Dc) / 16, 256>>>(dt, xn, Bv, Cv, A_log, Dp, scale, x, x2);
    // 5) xn2 = rmsnorm(x2, norm2_w)
    rmsnorm_kernel<<<TOK, 256>>>(x2, n2w, xn2);
    // 6) h = gelu(xn2 @ W1^T + b1)
    mma_gemm<2><<<dim3(Fc / 128, TOK / 128), 256, SMEM>>>(xn2, W1, b1, nullptr, hb, TOK, Fc, Dc);
    // 7) out = h @ W2^T + b2 + x2
    mma_gemm<3><<<dim3(Dc / 128, TOK / 128), 256, SMEM>>>(hb, W2, b2, x2, out, TOK, Dc, Fc);
}

// round 4
// speedup vs baseline: 1.7126x; 1.0219x over previous
#include <cuda_runtime.h>
#include <math.h>
#include <stdint.h>

// Problem constants (fixed by reference setup_inputs)
#define Bc   2
#define Lc   2048
#define Dc   1024
#define Nc   16
#define Fc   4096
#define TOK  (Bc*Lc)          // 4096 tokens
#define EPSF 1e-6f

// ---------------- scratch (no allocation allowed) ----------------
__device__ float g_xn [TOK*Dc];   // rmsnorm1 output
__device__ float g_dt [TOK*Dc];   // softplus(xn@Wdt^T+bdt)
__device__ float g_x2 [TOK*Dc];   // mamba out + residual
__device__ float g_xn2[TOK*Dc];   // rmsnorm2 output
__device__ float g_Bv [TOK*Nc];
__device__ float g_Cv [TOK*Nc];
__device__ float g_h  [TOK*Fc];   // FFN hidden

// ---------------- helpers ----------------
__device__ __forceinline__ float softplus_f(float v) {
    return fmaxf(v, 0.0f) + log1pf(__expf(-fabsf(v)));
}
__device__ __forceinline__ float gelu_f(float v) {
    const float c = 0.7978845608028654f; // sqrt(2/pi)
    float u = c * (v + 0.044715f * v * v * v);
    return 0.5f * v * (1.0f + tanhf(u));
}
__device__ __forceinline__ uint32_t f2tf(float x) {
    uint32_t r;
    asm("cvt.rna.tf32.f32 %0, %1;" : "=r"(r) : "f"(x));
    return r;
}
__device__ __forceinline__ void mma8(float* d, const uint32_t* a, const uint32_t* b) {
    asm volatile(
        "mma.sync.aligned.m16n8k8.row.col.f32.tf32.tf32.f32 "
        "{%0,%1,%2,%3}, {%4,%5,%6,%7}, {%8,%9}, {%0,%1,%2,%3};"
        : "+f"(d[0]), "+f"(d[1]), "+f"(d[2]), "+f"(d[3])
        : "r"(a[0]), "r"(a[1]), "r"(a[2]), "r"(a[3]), "r"(b[0]), "r"(b[1]));
}

#define CPA(s,g)      asm volatile("cp.async.cg.shared.global [%0], [%1], 16;" :: "r"(s), "l"(g))
#define CPA_COMMIT()  asm volatile("cp.async.commit_group;" ::: "memory")
#define CPA_WAIT1()   asm volatile("cp.async.wait_group 1;" ::: "memory")
#define CPA_WAIT0()   asm volatile("cp.async.wait_group 0;" ::: "memory")

__device__ __forceinline__ uint32_t smem_u32(const void* p) {
    uint32_t a;
    asm("{ .reg .u64 t; cvta.to.shared.u64 t, %1; cvt.u32.u64 %0, t; }" : "=r"(a) : "l"(p));
    return a;
}

// ---------------- rmsnorm: one block per token, 256 threads ----------------
__global__ void rmsnorm_kernel(const float* __restrict__ x,
                               const float* __restrict__ w,
                               float* __restrict__ out)
{
    __shared__ float red[8];
    const int t = blockIdx.x;
    const int tid = threadIdx.x;
    const float4 a = reinterpret_cast<const float4*>(x + (size_t)t * Dc)[tid];
    float ss = a.x*a.x + a.y*a.y + a.z*a.z + a.w*a.w;
#pragma unroll
    for (int o = 16; o; o >>= 1) ss += __shfl_xor_sync(0xffffffffu, ss, o);
    if ((tid & 31) == 0) red[tid >> 5] = ss;
    __syncthreads();
    if (tid < 8) {
        float v = red[tid];
#pragma unroll
        for (int o = 4; o; o >>= 1) v += __shfl_xor_sync(0xffu, v, o);
        if (tid == 0) red[0] = v;
    }
    __syncthreads();
    const float inv = rsqrtf(red[0] * (1.0f / Dc) + EPSF);
    const float4 wv = reinterpret_cast<const float4*>(w)[tid];
    float4 o4;
    o4.x = a.x * inv * wv.x;
    o4.y = a.y * inv * wv.y;
    o4.z = a.z * inv * wv.z;
    o4.w = a.w * inv * wv.w;
    reinterpret_cast<float4*>(out + (size_t)t * Dc)[tid] = o4;
}

// ---------------- mma.sync tf32 GEMM: C[M,Nout] = X[M,K] @ W[Nout,K]^T ----------------
// 128x128 CTA tile, BK=32, 8 warps (2x4), warp tile 64x32 (4x4 m16n8k8 frags).
// 3-stage cp.async pipeline, one __syncthreads per stage, 2 CTAs/SM.
// EPI: 1 = softplus(v+bias)  2 = gelu(v+bias)  3 = v+bias+res
#define LDST   36            // padded row stride (floats)
#define BUFSZ  (128 * LDST)  // one A or B buffer (floats)
#define NSTG   3

template<int EPI>
__global__ __launch_bounds__(256, 2)
void mma_gemm(const float* __restrict__ X, const float* __restrict__ W,
              const float* __restrict__ bias, const float* __restrict__ res,
              float* __restrict__ C, int M, int Nout, int K)
{
    extern __shared__ float sm[];
    float* As = sm;                        // [NSTG][BUFSZ]
    float* Bs = sm + NSTG * BUFSZ;         // [NSTG][BUFSZ]

    const int tid = threadIdx.x;
    const int wid = tid >> 5, lane = tid & 31;
    const int wm = wid >> 2, wn = wid & 3;         // 2 x 4 warp grid
    const int g = lane >> 2, tg = lane & 3;
    const int m0 = blockIdx.y * 128, n0 = blockIdx.x * 128;

    const uint32_t asmb = smem_u32(As);
    const uint32_t bsmb = smem_u32(Bs);

    auto load_stage = [&](int s, int buf) {
        const int k0 = s << 5;
        const uint32_t ab = asmb + (uint32_t)buf * (BUFSZ * 4);
        const uint32_t bb = bsmb + (uint32_t)buf * (BUFSZ * 4);
#pragma unroll
        for (int j = 0; j < 4; j++) {
            const int i = tid + (j << 8);          // 0..1023
            const int r = i >> 3, c = i & 7;       // row 0..127, float4 col 0..7
            const uint32_t so = (uint32_t)(r * LDST + c * 4) * 4u;
            CPA(ab + so, X + (size_t)(m0 + r) * K + k0 + c * 4);
            CPA(bb + so, W + (size_t)(n0 + r) * K + k0 + c * 4);
        }
        CPA_COMMIT();
    };

    float acc[4][4][4];
#pragma unroll
    for (int i = 0; i < 4; i++)
#pragma unroll
        for (int j = 0; j < 4; j++)
#pragma unroll
            for (int q = 0; q < 4; q++) acc[i][j][q] = 0.0f;

    const int S = K >> 5;
    load_stage(0, 0);
    load_stage(1, 1);

    for (int s = 0; s < S; s++) {
        // complete this thread's group for stage s (per-thread), then make all
        // threads' stage-s writes visible CTA-wide.
        if (s + 1 < S) CPA_WAIT1(); else CPA_WAIT0();
        __syncthreads();
        // prefetch stage s+2 into buffer (s+2)%3 == (s-1)%3; safe: everyone has
        // finished computing stage s-1 before passing the barrier above.
        if (s + 2 < S) load_stage(s + 2, (s + 2) % NSTG);

        const float* Ab = As + (s % NSTG) * BUFSZ;
        const float* Bb = Bs + (s % NSTG) * BUFSZ;
#pragma unroll
        for (int ks = 0; ks < 4; ks++) {
            uint32_t af[4][4], bf[4][2];
#pragma unroll
            for (int i = 0; i < 4; i++) {
                const float* p = Ab + (wm * 64 + i * 16 + g) * LDST + ks * 8 + tg;
                af[i][0] = f2tf(p[0]);
                af[i][1] = f2tf(p[8 * LDST]);
                af[i][2] = f2tf(p[4]);
                af[i][3] = f2tf(p[8 * LDST + 4]);
            }
#pragma unroll
            for (int j = 0; j < 4; j++) {
                const float* p = Bb + (wn * 32 + j * 8 + g) * LDST + ks * 8 + tg;
                bf[j][0] = f2tf(p[0]);
                bf[j][1] = f2tf(p[4]);
            }
#pragma unroll
            for (int i = 0; i < 4; i++)
#pragma unroll
                for (int j = 0; j < 4; j++) mma8(acc[i][j], af[i], bf[j]);
        }
    }

    // Epilogue: c0,c1 at (row g, cols 2tg,2tg+1); c2,c3 at row g+8.
#pragma unroll
    for (int i = 0; i < 4; i++) {
        const int mA = m0 + wm * 64 + i * 16 + g;
#pragma unroll
        for (int j = 0; j < 4; j++) {
            const int nA = n0 + wn * 32 + j * 8 + tg * 2;
            const float2 bb = *reinterpret_cast<const float2*>(bias + nA);
#pragma unroll
            for (int h = 0; h < 2; h++) {
                const int m = mA + h * 8;
                float v0 = acc[i][j][h * 2 + 0] + bb.x;
                float v1 = acc[i][j][h * 2 + 1] + bb.y;
                if (EPI == 1) { v0 = softplus_f(v0); v1 = softplus_f(v1); }
                else if (EPI == 2) { v0 = gelu_f(v0); v1 = gelu_f(v1); }
                else if (EPI == 3) {
                    const float2 r2 = *reinterpret_cast<const float2*>(res + (size_t)m * Nout + nA);
                    v0 += r2.x; v1 += r2.y;
                }
                *reinterpret_cast<float2*>(C + (size_t)m * Nout + nA) = make_float2(v0, v1);
            }
        }
    }
}

// ---------------- B/C projections: one block per token ----------------
__global__ void bc_kernel(const float* __restrict__ xn,
                          const float* __restrict__ WB, const float* __restrict__ bB,
                          const float* __restrict__ WC, const float* __restrict__ bC,
                          float* __restrict__ Bv, float* __restrict__ Cv)
{
    __shared__ float xs[Dc];
    const int t = blockIdx.x;
    const int tid = threadIdx.x;
    reinterpret_cast<float4*>(xs)[tid] =
        reinterpret_cast<const float4*>(xn + (size_t)t * Dc)[tid];
    __syncthreads();

    const int o = tid >> 3;
    const int p = tid & 7;
    const float* w = (o < Nc) ? (WB + (size_t)o * Dc) : (WC + (size_t)(o - Nc) * Dc);
    float s = 0.0f;
#pragma unroll 8
    for (int k = p; k < Dc; k += 8) s = fmaf(xs[k], w[k], s);
    s += __shfl_xor_sync(0xffffffffu, s, 1);
    s += __shfl_xor_sync(0xffffffffu, s, 2);
    s += __shfl_xor_sync(0xffffffffu, s, 4);
    if (p == 0) {
        if (o < Nc) Bv[(size_t)t * Nc + o] = s + bB[o];
        else        Cv[(size_t)t * Nc + (o - Nc)] = s + bC[o - Nc];
    }
}

// ---------------- selective scan: lane per (b,d,n), 16-lane segments ----------------
// 256 blocks x 128 threads -> covers all 148 SMs.
__global__ void scan_kernel(const float* __restrict__ dt, const float* __restrict__ xn,
                            const float* __restrict__ Bv, const float* __restrict__ Cv,
                            const float* __restrict__ A_log, const float* __restrict__ Dp,
                            const float* __restrict__ scale, const float* __restrict__ resid,
                            float* __restrict__ out)
{
    const int tid = threadIdx.x;
    const int n = tid & 15;
    const int g = blockIdx.x * (blockDim.x >> 4) + (tid >> 4); // (b,d) group, 0..2047
    const int b = g >> 10;
    const int d = g & 1023;

    const float An  = -__expf(A_log[n]);
    const float Dpv = Dp[d];
    const float sc  = scale[d];

    const float* dtp = dt    + (size_t)b * Lc * Dc + d;
    const float* xnp = xn    + (size_t)b * Lc * Dc + d;
    const float* rpp = resid + (size_t)b * Lc * Dc + d;
    float*       opp = out   + (size_t)b * Lc * Dc + d;
    const float* bpp = Bv    + (size_t)b * Lc * Nc + n;
    const float* cpp = Cv    + (size_t)b * Lc * Nc + n;

    float h = 0.0f;
#pragma unroll 2
    for (int l = 0; l < Lc; l++) {
        const float dtv = dtp[(size_t)l * Dc];
        const float xv  = xnp[(size_t)l * Dc];
        const float bv  = bpp[(size_t)l * Nc];
        const float cv  = cpp[(size_t)l * Nc];

        const float z = dtv * An;
        const float e = __expf(z);
        const float phi = (fabsf(z) < 1e-4f) ? fmaf(0.5f, z, 1.0f)
                                             : __fdividef(e - 1.0f, z);
        h = fmaf(e, h, phi * bv * xv);

        float p = cv * h;
        p += __shfl_xor_sync(0xffffffffu, p, 1);
        p += __shfl_xor_sync(0xffffffffu, p, 2);
        p += __shfl_xor_sync(0xffffffffu, p, 4);
        p += __shfl_xor_sync(0xffffffffu, p, 8);
        if (n == 0) {
            const float r = rpp[(size_t)l * Dc];
            opp[(size_t)l * Dc] = fmaf(fmaf(Dpv, xv, p), sc, r);
        }
    }
}

// ---------------- launch ----------------
extern "C" void kernel_launch(void* const* d_in, const int* in_sizes, int n_in,
                              void* d_out, int out_size)
{
    const float* x     = (const float*)d_in[0];
    const float* n1w   = (const float*)d_in[1];
    const float* n2w   = (const float*)d_in[2];
    const float* A_log = (const float*)d_in[3];
    const float* Dp    = (const float*)d_in[4];
    const float* scale = (const float*)d_in[5];
    const float* Wdt   = (const float*)d_in[6];
    const float* bdt   = (const float*)d_in[7];
    const float* WB    = (const float*)d_in[8];
    const float* bB    = (const float*)d_in[9];
    const float* WC    = (const float*)d_in[10];
    const float* bC    = (const float*)d_in[11];
    const float* W1    = (const float*)d_in[12];
    const float* b1    = (const float*)d_in[13];
    const float* W2    = (const float*)d_in[14];
    const float* b2    = (const float*)d_in[15];
    float* out = (float*)d_out;

    float *xn, *dt, *x2, *xn2, *Bv, *Cv, *hb;
    cudaGetSymbolAddress((void**)&xn,  g_xn);
    cudaGetSymbolAddress((void**)&dt,  g_dt);
    cudaGetSymbolAddress((void**)&x2,  g_x2);
    cudaGetSymbolAddress((void**)&xn2, g_xn2);
    cudaGetSymbolAddress((void**)&Bv,  g_Bv);
    cudaGetSymbolAddress((void**)&Cv,  g_Cv);
    cudaGetSymbolAddress((void**)&hb,  g_h);

    const int SMEM = 2 * NSTG * BUFSZ * 4;   // 110592 B
    cudaFuncSetAttribute(mma_gemm<1>, cudaFuncAttributeMaxDynamicSharedMemorySize, SMEM);
    cudaFuncSetAttribute(mma_gemm<2>, cudaFuncAttributeMaxDynamicSharedMemorySize, SMEM);
    cudaFuncSetAttribute(mma_gemm<3>, cudaFuncAttributeMaxDynamicSharedMemorySize, SMEM);

    // 1) xn = rmsnorm(x, norm1_w)
    rmsnorm_kernel<<<TOK, 256>>>(x, n1w, xn);
    // 2) dt = softplus(xn @ Wdt^T + bdt)
    mma_gemm<1><<<dim3(Dc / 128, TOK / 128), 256, SMEM>>>(xn, Wdt, bdt, nullptr, dt, TOK, Dc, Dc);
    // 3) Bv, Cv projections
    bc_kernel<<<TOK, 256>>>(xn, WB, bB, WC, bC, Bv, Cv);
    // 4) selective scan + D-skip + scale + residual -> x2
    scan_kernel<<<(Bc * Dc) / 8, 128>>>(dt, xn, Bv, Cv, A_log, Dp, scale, x, x2);
    // 5) xn2 = rmsnorm(x2, norm2_w)
    rmsnorm_kernel<<<TOK, 256>>>(x2, n2w, xn2);
    // 6) h = gelu(xn2 @ W1^T + b1)
    mma_gemm<2><<<dim3(Fc / 128, TOK / 128), 256, SMEM>>>(xn2, W1, b1, nullptr, hb, TOK, Fc, Dc);
    // 7) out = h @ W2^T + b2 + x2
    mma_gemm<3><<<dim3(Dc / 128, TOK / 128), 256, SMEM>>>(hb, W2, b2, x2, out, TOK, Dc, Fc);
}